// round 6
// baseline (speedup 1.0000x reference)
#include <cuda_runtime.h>
#include <cuda_bf16.h>
#include <cstdint>

#define NN 50000
#define NE 1600000
#define DIM 128
#define DOUT 64
#define NB_SCAN 49   // ceil(50000/1024)

// ---------------- scratch (device globals; no allocations allowed) ----------
__device__ int   g_is32;                     // 1 if edge_index is int32
__device__ int   g_deg[NN];
__device__ int   g_off[NN];
__device__ int   g_cur[NN];
__device__ int   g_bsum[64];
__device__ int   g_csr[NE];
__device__ __align__(16) float g_agg1[(size_t)NN * DIM];   // mean-agg x    [N,128]
__device__ __align__(16) float g_h   [(size_t)NN * DIM];   // relu(layer1)  [N,128]
__device__ __align__(16) float g_pr  [(size_t)NN * DIM];   // [h@W2l|h@W2r] [N,128]
__device__ __align__(16) float g_agg2[(size_t)NN * DOUT];  // mean-agg p    [N,64]

// ---------------- dtype detection -------------------------------------------
// int64 edge ids < 50000 => every odd 32-bit word (high half) is 0.
// int32 edge ids => odd words are ~uniform in [0,50000): virtually all nonzero.
__global__ void k_detect(const unsigned* __restrict__ w) {
    if (threadIdx.x == 0) g_is32 = 0;
    __syncthreads();
    int found = 0;
    for (int i = threadIdx.x; i < 1024; i += blockDim.x)
        if (w[2 * i + 1] != 0u) found = 1;
    if (found) atomicOr(&g_is32, 1);
}

// ---------------- CSR construction ------------------------------------------
__global__ void k_zero() {
    int i = blockIdx.x * blockDim.x + threadIdx.x;
    if (i < NN) g_deg[i] = 0;
}

__global__ void k_deg(const int* __restrict__ e32,
                      const long long* __restrict__ e64) {
    int e = blockIdx.x * blockDim.x + threadIdx.x;
    if (e >= NE) return;
    int d = g_is32 ? e32[NE + e] : (int)e64[NE + e];   // dst row
    if ((unsigned)d < NN) atomicAdd(&g_deg[d], 1);
}

__global__ void k_scanA() {
    __shared__ int wsum[32];
    int i = blockIdx.x * 1024 + threadIdx.x;
    int v = (i < NN) ? g_deg[i] : 0;
    int lane = threadIdx.x & 31, wid = threadIdx.x >> 5;
    int s = v;
#pragma unroll
    for (int o = 1; o < 32; o <<= 1) {
        int t = __shfl_up_sync(0xffffffffu, s, o);
        if (lane >= o) s += t;
    }
    if (lane == 31) wsum[wid] = s;
    __syncthreads();
    if (wid == 0) {
        int ws = wsum[lane];
#pragma unroll
        for (int o = 1; o < 32; o <<= 1) {
            int t = __shfl_up_sync(0xffffffffu, ws, o);
            if (lane >= o) ws += t;
        }
        wsum[lane] = ws;
    }
    __syncthreads();
    int base = wid ? wsum[wid - 1] : 0;
    if (i < NN) g_off[i] = base + s - v;          // exclusive within block
    if (threadIdx.x == 0) g_bsum[blockIdx.x] = wsum[31];
}

__global__ void k_scanB() {
    if (threadIdx.x == 0 && blockIdx.x == 0) {
        int acc = 0;
        for (int b = 0; b < NB_SCAN; b++) { int t = g_bsum[b]; g_bsum[b] = acc; acc += t; }
    }
}

__global__ void k_scanC() {
    int i = blockIdx.x * 1024 + threadIdx.x;
    if (i < NN) {
        int o = g_off[i] + g_bsum[blockIdx.x];
        g_off[i] = o;
        g_cur[i] = o;
    }
}

__global__ void k_scatter(const int* __restrict__ e32,
                          const long long* __restrict__ e64) {
    int e = blockIdx.x * blockDim.x + threadIdx.x;
    if (e >= NE) return;
    int s, d;
    if (g_is32) { s = e32[e]; d = e32[NE + e]; }
    else        { s = (int)e64[e]; d = (int)e64[NE + e]; }
    if ((unsigned)d < NN) {
        int pos = atomicAdd(&g_cur[d], 1);
        g_csr[pos] = ((unsigned)s < NN) ? s : 0;
    }
}

// ---------------- aggregation (warp per node, CSR gather) -------------------
__global__ void k_agg128(const float* __restrict__ src) {
    int w = (blockIdx.x * blockDim.x + threadIdx.x) >> 5;
    if (w >= NN) return;
    int lane = threadIdx.x & 31;
    int start = g_off[w];
    int d = g_deg[w];
    const float4* sv = (const float4*)src;
    float4 a0 = make_float4(0.f, 0.f, 0.f, 0.f);
    float4 a1 = make_float4(0.f, 0.f, 0.f, 0.f);
    for (int j = 0; j < d; j += 32) {
        int m = min(32, d - j);
        int sidx = (j + lane < d) ? g_csr[start + j + lane] : 0;
        int jj = 0;
        for (; jj + 2 <= m; jj += 2) {
            int s0 = __shfl_sync(0xffffffffu, sidx, jj);
            int s1 = __shfl_sync(0xffffffffu, sidx, jj + 1);
            float4 v0 = sv[(size_t)s0 * 32 + lane];
            float4 v1 = sv[(size_t)s1 * 32 + lane];
            a0.x += v0.x; a0.y += v0.y; a0.z += v0.z; a0.w += v0.w;
            a1.x += v1.x; a1.y += v1.y; a1.z += v1.z; a1.w += v1.w;
        }
        if (jj < m) {
            int s0 = __shfl_sync(0xffffffffu, sidx, jj);
            float4 v0 = sv[(size_t)s0 * 32 + lane];
            a0.x += v0.x; a0.y += v0.y; a0.z += v0.z; a0.w += v0.w;
        }
    }
    float inv = 1.0f / (float)max(d, 1);
    float4 r;
    r.x = (a0.x + a1.x) * inv;
    r.y = (a0.y + a1.y) * inv;
    r.z = (a0.z + a1.z) * inv;
    r.w = (a0.w + a1.w) * inv;
    ((float4*)g_agg1)[(size_t)w * 32 + lane] = r;
}

// aggregate first 64 cols of g_pr (the h@W2_l projection) -> g_agg2
__global__ void k_agg64() {
    int w = (blockIdx.x * blockDim.x + threadIdx.x) >> 5;
    if (w >= NN) return;
    int lane = threadIdx.x & 31;
    int start = g_off[w];
    int d = g_deg[w];
    const float2* sv = (const float2*)g_pr;   // 128 floats = 64 float2 per row
    float2 a0 = make_float2(0.f, 0.f);
    float2 a1 = make_float2(0.f, 0.f);
    for (int j = 0; j < d; j += 32) {
        int m = min(32, d - j);
        int sidx = (j + lane < d) ? g_csr[start + j + lane] : 0;
        int jj = 0;
        for (; jj + 2 <= m; jj += 2) {
            int s0 = __shfl_sync(0xffffffffu, sidx, jj);
            int s1 = __shfl_sync(0xffffffffu, sidx, jj + 1);
            float2 v0 = sv[(size_t)s0 * 64 + lane];   // cols 0..63
            float2 v1 = sv[(size_t)s1 * 64 + lane];
            a0.x += v0.x; a0.y += v0.y;
            a1.x += v1.x; a1.y += v1.y;
        }
        if (jj < m) {
            int s0 = __shfl_sync(0xffffffffu, sidx, jj);
            float2 v0 = sv[(size_t)s0 * 64 + lane];
            a0.x += v0.x; a0.y += v0.y;
        }
    }
    float inv = 1.0f / (float)max(d, 1);
    float2 r;
    r.x = (a0.x + a1.x) * inv;
    r.y = (a0.y + a1.y) * inv;
    ((float2*)g_agg2)[(size_t)w * 32 + lane] = r;
}

// ---------------- GEMM 1: g_h = relu(g_agg1@W1_l + x@W1_r + b1) -------------
// Treated as C = relu([agg1|x] @ [W1_l;W1_r] + b1), K=256, N=128.
__global__ __launch_bounds__(256) void k_gemm1(
    const float* __restrict__ x,
    const float* __restrict__ Wl, const float* __restrict__ Wr,
    const float* __restrict__ bias) {
    __shared__ float As[16][128];
    __shared__ float Bs[16][128];
    const int tid = threadIdx.x;
    const int bm = blockIdx.x * 128;
    const int trow = (tid >> 4) * 8;
    const int tcol = (tid & 15) * 8;
    float acc[8][8];
#pragma unroll
    for (int i = 0; i < 8; i++)
#pragma unroll
        for (int j = 0; j < 8; j++) acc[i][j] = 0.f;

    for (int kc = 0; kc < 256; kc += 16) {
#pragma unroll
        for (int q = 0; q < 2; q++) {
            int slot = tid * 2 + q;
            int r = slot >> 2;
            int c = (slot & 3) * 4;
            int row = bm + r;
            int k = kc + c;
            float4 v = make_float4(0.f, 0.f, 0.f, 0.f);
            if (row < NN) {
                const float* s = (k < 128) ? (g_agg1 + (size_t)row * 128 + k)
                                           : (x + (size_t)row * 128 + (k - 128));
                v = *(const float4*)s;
            }
            As[c + 0][r] = v.x; As[c + 1][r] = v.y;
            As[c + 2][r] = v.z; As[c + 3][r] = v.w;
        }
#pragma unroll
        for (int q = 0; q < 2; q++) {
            int slot = tid * 2 + q;
            int r = slot >> 5;
            int c = (slot & 31) * 4;
            int k = kc + r;
            const float* s = (k < 128) ? (Wl + (size_t)k * 128 + c)
                                       : (Wr + (size_t)(k - 128) * 128 + c);
            *(float4*)&Bs[r][c] = *(const float4*)s;
        }
        __syncthreads();
#pragma unroll
        for (int k = 0; k < 16; k++) {
            float a[8], b[8];
            *(float4*)&a[0] = *(const float4*)&As[k][trow];
            *(float4*)&a[4] = *(const float4*)&As[k][trow + 4];
            *(float4*)&b[0] = *(const float4*)&Bs[k][tcol];
            *(float4*)&b[4] = *(const float4*)&Bs[k][tcol + 4];
#pragma unroll
            for (int i = 0; i < 8; i++)
#pragma unroll
                for (int j = 0; j < 8; j++)
                    acc[i][j] = fmaf(a[i], b[j], acc[i][j]);
        }
        __syncthreads();
    }
    float bv[8];
    *(float4*)&bv[0] = *(const float4*)&bias[tcol];
    *(float4*)&bv[4] = *(const float4*)&bias[tcol + 4];
#pragma unroll
    for (int i = 0; i < 8; i++) {
        int row = bm + trow + i;
        if (row < NN) {
#pragma unroll
            for (int j = 0; j < 8; j += 4) {
                float4 o;
                o.x = fmaxf(acc[i][j + 0] + bv[j + 0], 0.f);
                o.y = fmaxf(acc[i][j + 1] + bv[j + 1], 0.f);
                o.z = fmaxf(acc[i][j + 2] + bv[j + 2], 0.f);
                o.w = fmaxf(acc[i][j + 3] + bv[j + 3], 0.f);
                *(float4*)&g_h[(size_t)row * 128 + tcol + j] = o;
            }
        }
    }
}

// ---------------- GEMM 2: g_pr = g_h @ [W2_l | W2_r], K=128, N=128 ----------
__global__ __launch_bounds__(256) void k_gemm2(
    const float* __restrict__ W2l, const float* __restrict__ W2r) {
    __shared__ float As[16][128];
    __shared__ float Bs[16][128];
    const int tid = threadIdx.x;
    const int bm = blockIdx.x * 128;
    const int trow = (tid >> 4) * 8;
    const int tcol = (tid & 15) * 8;
    float acc[8][8];
#pragma unroll
    for (int i = 0; i < 8; i++)
#pragma unroll
        for (int j = 0; j < 8; j++) acc[i][j] = 0.f;

    for (int kc = 0; kc < 128; kc += 16) {
#pragma unroll
        for (int q = 0; q < 2; q++) {
            int slot = tid * 2 + q;
            int r = slot >> 2;
            int c = (slot & 3) * 4;
            int row = bm + r;
            float4 v = make_float4(0.f, 0.f, 0.f, 0.f);
            if (row < NN) v = *(const float4*)(g_h + (size_t)row * 128 + kc + c);
            As[c + 0][r] = v.x; As[c + 1][r] = v.y;
            As[c + 2][r] = v.z; As[c + 3][r] = v.w;
        }
#pragma unroll
        for (int q = 0; q < 2; q++) {
            int slot = tid * 2 + q;
            int r = slot >> 5;
            int c = (slot & 31) * 4;
            int k = kc + r;
            const float* s = (c < 64) ? (W2l + (size_t)k * 64 + c)
                                      : (W2r + (size_t)k * 64 + (c - 64));
            *(float4*)&Bs[r][c] = *(const float4*)s;
        }
        __syncthreads();
#pragma unroll
        for (int k = 0; k < 16; k++) {
            float a[8], b[8];
            *(float4*)&a[0] = *(const float4*)&As[k][trow];
            *(float4*)&a[4] = *(const float4*)&As[k][trow + 4];
            *(float4*)&b[0] = *(const float4*)&Bs[k][tcol];
            *(float4*)&b[4] = *(const float4*)&Bs[k][tcol + 4];
#pragma unroll
            for (int i = 0; i < 8; i++)
#pragma unroll
                for (int j = 0; j < 8; j++)
                    acc[i][j] = fmaf(a[i], b[j], acc[i][j]);
        }
        __syncthreads();
    }
#pragma unroll
    for (int i = 0; i < 8; i++) {
        int row = bm + trow + i;
        if (row < NN) {
#pragma unroll
            for (int j = 0; j < 8; j += 4) {
                float4 o;
                o.x = acc[i][j + 0]; o.y = acc[i][j + 1];
                o.z = acc[i][j + 2]; o.w = acc[i][j + 3];
                *(float4*)&g_pr[(size_t)row * 128 + tcol + j] = o;
            }
        }
    }
}

// ---------------- final: out = agg2 + r-part(g_pr) + b2 ---------------------
__global__ void k_final(const float* __restrict__ b2, float* __restrict__ out) {
    int v = blockIdx.x * blockDim.x + threadIdx.x;   // over NN*16 float4s
    if (v >= NN * 16) return;
    int row = v >> 4;
    int c4 = v & 15;
    float4 a = ((const float4*)g_agg2)[v];
    float4 r = ((const float4*)g_pr)[(size_t)row * 32 + 16 + c4];
    float4 bb = ((const float4*)b2)[c4];
    float4 o;
    o.x = a.x + r.x + bb.x;
    o.y = a.y + r.y + bb.y;
    o.z = a.z + r.z + bb.z;
    o.w = a.w + r.w + bb.w;
    ((float4*)out)[v] = o;
}

// ---------------- launch ----------------------------------------------------
extern "C" void kernel_launch(void* const* d_in, const int* in_sizes, int n_in,
                              void* d_out, int out_size) {
    const float*     x   = (const float*)d_in[0];
    const int*       e32 = (const int*)d_in[1];
    const long long* e64 = (const long long*)d_in[1];
    const unsigned*  ew  = (const unsigned*)d_in[1];
    const float*     W1l = (const float*)d_in[2];
    const float*     W1r = (const float*)d_in[3];
    const float*     b1  = (const float*)d_in[4];
    const float*     W2l = (const float*)d_in[5];
    const float*     W2r = (const float*)d_in[6];
    const float*     b2  = (const float*)d_in[7];
    float*           out = (float*)d_out;

    k_detect<<<1, 256>>>(ew);
    k_zero<<<(NN + 255) / 256, 256>>>();
    k_deg<<<(NE + 255) / 256, 256>>>(e32, e64);
    k_scanA<<<NB_SCAN, 1024>>>();
    k_scanB<<<1, 32>>>();
    k_scanC<<<NB_SCAN, 1024>>>();
    k_scatter<<<(NE + 255) / 256, 256>>>(e32, e64);

    k_agg128<<<(NN * 32 + 255) / 256, 256>>>(x);                 // agg1 = mean(x)
    k_gemm1<<<(NN + 127) / 128, 256>>>(x, W1l, W1r, b1);         // h
    k_gemm2<<<(NN + 127) / 128, 256>>>(W2l, W2r);                // pr = h@[W2l|W2r]
    k_agg64<<<(NN * 32 + 255) / 256, 256>>>();                   // agg2 = mean(p)
    k_final<<<(NN * 16 + 255) / 256, 256>>>(b2, out);            // out
}

// round 7
// speedup vs baseline: 1.1184x; 1.1184x over previous
#include <cuda_runtime.h>
#include <cuda_bf16.h>
#include <cstdint>

#define NN 50000
#define NE 1600000
#define DIM 128
#define DOUT 64
#define NB_SCAN 49   // ceil(50000/1024)

// ---------------- scratch (device globals; no allocations allowed) ----------
__device__ int   g_is32;                     // 1 if edge_index is int32
__device__ int   g_deg[NN];
__device__ int   g_off[NN];
__device__ int   g_cur[NN];
__device__ int   g_bsum[64];
__device__ int   g_csr[NE];
__device__ __align__(16) float g_agg1[(size_t)NN * DIM];   // mean-agg x    [N,128]
__device__ __align__(16) float g_h   [(size_t)NN * DIM];   // relu(layer1)  [N,128]
__device__ __align__(16) float g_pr  [(size_t)NN * DIM];   // [h@W2l|h@W2r] [N,128]

// ---------------- f32x2 packed helpers (sm_103a) -----------------------------
__device__ __forceinline__ unsigned long long ffma2(unsigned long long a,
                                                    unsigned long long b,
                                                    unsigned long long c) {
    unsigned long long d;
    asm("fma.rn.f32x2 %0, %1, %2, %3;" : "=l"(d) : "l"(a), "l"(b), "l"(c));
    return d;
}
__device__ __forceinline__ unsigned long long pack2(float lo, float hi) {
    unsigned long long d;
    asm("mov.b64 %0, {%1, %2};" : "=l"(d) : "f"(lo), "f"(hi));
    return d;
}
__device__ __forceinline__ unsigned long long dup2(float v) {
    unsigned long long d;
    asm("mov.b64 %0, {%1, %1};" : "=l"(d) : "f"(v));
    return d;
}
__device__ __forceinline__ void unpack2(unsigned long long p, float& lo, float& hi) {
    asm("mov.b64 {%0, %1}, %2;" : "=f"(lo), "=f"(hi) : "l"(p));
}

// ---------------- dtype detection -------------------------------------------
// int64 edge ids < 50000 => every odd 32-bit word (high half) is 0.
// int32 edge ids => odd words ~uniform in [0,50000): virtually all nonzero.
__global__ void k_detect(const unsigned* __restrict__ w) {
    if (threadIdx.x == 0) g_is32 = 0;
    __syncthreads();
    int found = 0;
    for (int i = threadIdx.x; i < 1024; i += blockDim.x)
        if (w[2 * i + 1] != 0u) found = 1;
    if (found) atomicOr(&g_is32, 1);
}

// ---------------- CSR construction ------------------------------------------
__global__ void k_zero() {
    int i = blockIdx.x * blockDim.x + threadIdx.x;
    if (i < NN) g_deg[i] = 0;
}

// 4 edges per thread, vectorized loads
__global__ void k_deg(const int* __restrict__ e32,
                      const long long* __restrict__ e64) {
    int base = (blockIdx.x * blockDim.x + threadIdx.x) * 4;
    if (base >= NE) return;
    int d0, d1, d2, d3;
    if (g_is32) {
        int4 v = *(const int4*)(e32 + NE + base);
        d0 = v.x; d1 = v.y; d2 = v.z; d3 = v.w;
    } else {
        longlong2 v0 = *(const longlong2*)(e64 + NE + base);
        longlong2 v1 = *(const longlong2*)(e64 + NE + base + 2);
        d0 = (int)v0.x; d1 = (int)v0.y; d2 = (int)v1.x; d3 = (int)v1.y;
    }
    if ((unsigned)d0 < NN) atomicAdd(&g_deg[d0], 1);
    if ((unsigned)d1 < NN) atomicAdd(&g_deg[d1], 1);
    if ((unsigned)d2 < NN) atomicAdd(&g_deg[d2], 1);
    if ((unsigned)d3 < NN) atomicAdd(&g_deg[d3], 1);
}

__global__ void k_scanA() {
    __shared__ int wsum[32];
    int i = blockIdx.x * 1024 + threadIdx.x;
    int v = (i < NN) ? g_deg[i] : 0;
    int lane = threadIdx.x & 31, wid = threadIdx.x >> 5;
    int s = v;
#pragma unroll
    for (int o = 1; o < 32; o <<= 1) {
        int t = __shfl_up_sync(0xffffffffu, s, o);
        if (lane >= o) s += t;
    }
    if (lane == 31) wsum[wid] = s;
    __syncthreads();
    if (wid == 0) {
        int ws = wsum[lane];
#pragma unroll
        for (int o = 1; o < 32; o <<= 1) {
            int t = __shfl_up_sync(0xffffffffu, ws, o);
            if (lane >= o) ws += t;
        }
        wsum[lane] = ws;
    }
    __syncthreads();
    int base = wid ? wsum[wid - 1] : 0;
    if (i < NN) g_off[i] = base + s - v;          // exclusive within block
    if (threadIdx.x == 0) g_bsum[blockIdx.x] = wsum[31];
}

__global__ void k_scanB() {
    if (threadIdx.x == 0 && blockIdx.x == 0) {
        int acc = 0;
        for (int b = 0; b < NB_SCAN; b++) { int t = g_bsum[b]; g_bsum[b] = acc; acc += t; }
    }
}

__global__ void k_scanC() {
    int i = blockIdx.x * 1024 + threadIdx.x;
    if (i < NN) {
        int o = g_off[i] + g_bsum[blockIdx.x];
        g_off[i] = o;
        g_cur[i] = o;
    }
}

__global__ void k_scatter(const int* __restrict__ e32,
                          const long long* __restrict__ e64) {
    int base = (blockIdx.x * blockDim.x + threadIdx.x) * 4;
    if (base >= NE) return;
    int s0, s1, s2, s3, d0, d1, d2, d3;
    if (g_is32) {
        int4 sv = *(const int4*)(e32 + base);
        int4 dv = *(const int4*)(e32 + NE + base);
        s0 = sv.x; s1 = sv.y; s2 = sv.z; s3 = sv.w;
        d0 = dv.x; d1 = dv.y; d2 = dv.z; d3 = dv.w;
    } else {
        longlong2 sa = *(const longlong2*)(e64 + base);
        longlong2 sb = *(const longlong2*)(e64 + base + 2);
        longlong2 da = *(const longlong2*)(e64 + NE + base);
        longlong2 db = *(const longlong2*)(e64 + NE + base + 2);
        s0 = (int)sa.x; s1 = (int)sa.y; s2 = (int)sb.x; s3 = (int)sb.y;
        d0 = (int)da.x; d1 = (int)da.y; d2 = (int)db.x; d3 = (int)db.y;
    }
    if ((unsigned)d0 < NN) g_csr[atomicAdd(&g_cur[d0], 1)] = ((unsigned)s0 < NN) ? s0 : 0;
    if ((unsigned)d1 < NN) g_csr[atomicAdd(&g_cur[d1], 1)] = ((unsigned)s1 < NN) ? s1 : 0;
    if ((unsigned)d2 < NN) g_csr[atomicAdd(&g_cur[d2], 1)] = ((unsigned)s2 < NN) ? s2 : 0;
    if ((unsigned)d3 < NN) g_csr[atomicAdd(&g_cur[d3], 1)] = ((unsigned)s3 < NN) ? s3 : 0;
}

// ---------------- aggregation (warp per node, CSR gather) -------------------
__global__ void k_agg128(const float* __restrict__ src) {
    int w = (blockIdx.x * blockDim.x + threadIdx.x) >> 5;
    if (w >= NN) return;
    int lane = threadIdx.x & 31;
    int start = g_off[w];
    int d = g_deg[w];
    const float4* sv = (const float4*)src;
    float4 a0 = make_float4(0.f, 0.f, 0.f, 0.f);
    float4 a1 = make_float4(0.f, 0.f, 0.f, 0.f);
    for (int j = 0; j < d; j += 32) {
        int m = min(32, d - j);
        int sidx = (j + lane < d) ? g_csr[start + j + lane] : 0;
        int jj = 0;
        for (; jj + 2 <= m; jj += 2) {
            int s0 = __shfl_sync(0xffffffffu, sidx, jj);
            int s1 = __shfl_sync(0xffffffffu, sidx, jj + 1);
            float4 v0 = sv[(size_t)s0 * 32 + lane];
            float4 v1 = sv[(size_t)s1 * 32 + lane];
            a0.x += v0.x; a0.y += v0.y; a0.z += v0.z; a0.w += v0.w;
            a1.x += v1.x; a1.y += v1.y; a1.z += v1.z; a1.w += v1.w;
        }
        if (jj < m) {
            int s0 = __shfl_sync(0xffffffffu, sidx, jj);
            float4 v0 = sv[(size_t)s0 * 32 + lane];
            a0.x += v0.x; a0.y += v0.y; a0.z += v0.z; a0.w += v0.w;
        }
    }
    float inv = 1.0f / (float)max(d, 1);
    float4 r;
    r.x = (a0.x + a1.x) * inv;
    r.y = (a0.y + a1.y) * inv;
    r.z = (a0.z + a1.z) * inv;
    r.w = (a0.w + a1.w) * inv;
    ((float4*)g_agg1)[(size_t)w * 32 + lane] = r;
}

// aggregate first 64 cols of g_pr (h@W2_l) + add self term + bias -> out
__global__ void k_agg64f(const float* __restrict__ b2, float* __restrict__ out) {
    int w = (blockIdx.x * blockDim.x + threadIdx.x) >> 5;
    if (w >= NN) return;
    int lane = threadIdx.x & 31;
    int start = g_off[w];
    int d = g_deg[w];
    const float2* sv = (const float2*)g_pr;   // 128 floats = 64 float2 per row
    float2 a0 = make_float2(0.f, 0.f);
    float2 a1 = make_float2(0.f, 0.f);
    for (int j = 0; j < d; j += 32) {
        int m = min(32, d - j);
        int sidx = (j + lane < d) ? g_csr[start + j + lane] : 0;
        int jj = 0;
        for (; jj + 2 <= m; jj += 2) {
            int s0 = __shfl_sync(0xffffffffu, sidx, jj);
            int s1 = __shfl_sync(0xffffffffu, sidx, jj + 1);
            float2 v0 = sv[(size_t)s0 * 64 + lane];   // cols 0..63
            float2 v1 = sv[(size_t)s1 * 64 + lane];
            a0.x += v0.x; a0.y += v0.y;
            a1.x += v1.x; a1.y += v1.y;
        }
        if (jj < m) {
            int s0 = __shfl_sync(0xffffffffu, sidx, jj);
            float2 v0 = sv[(size_t)s0 * 64 + lane];
            a0.x += v0.x; a0.y += v0.y;
        }
    }
    float inv = 1.0f / (float)max(d, 1);
    float2 selfr = sv[(size_t)w * 64 + 32 + lane];    // cols 64..127 (h@W2_r)
    float2 bb = ((const float2*)b2)[lane];
    float2 o;
    o.x = (a0.x + a1.x) * inv + selfr.x + bb.x;
    o.y = (a0.y + a1.y) * inv + selfr.y + bb.y;
    ((float2*)out)[(size_t)w * 32 + lane] = o;
}

// ---------------- GEMM 1: g_h = relu(g_agg1@W1_l + x@W1_r + b1) -------------
// C = relu([agg1|x] @ [W1_l;W1_r] + b1), K=256, N=128. f32x2 inner loop.
__global__ __launch_bounds__(256) void k_gemm1(
    const float* __restrict__ x,
    const float* __restrict__ Wl, const float* __restrict__ Wr,
    const float* __restrict__ bias) {
    __shared__ float As[16][128];
    __shared__ float Bs[16][128];
    const int tid = threadIdx.x;
    const int bm = blockIdx.x * 128;
    const int trow = (tid >> 4) * 8;
    const int tcol = (tid & 15) * 8;
    unsigned long long acc2[4][8];    // packed rows (trow+2p, trow+2p+1) x col j
#pragma unroll
    for (int p = 0; p < 4; p++)
#pragma unroll
        for (int j = 0; j < 8; j++) acc2[p][j] = 0ull;

    for (int kc = 0; kc < 256; kc += 16) {
#pragma unroll
        for (int q = 0; q < 2; q++) {
            int slot = tid * 2 + q;
            int r = slot >> 2;
            int c = (slot & 3) * 4;
            int row = bm + r;
            int k = kc + c;
            float4 v = make_float4(0.f, 0.f, 0.f, 0.f);
            if (row < NN) {
                const float* s = (k < 128) ? (g_agg1 + (size_t)row * 128 + k)
                                           : (x + (size_t)row * 128 + (k - 128));
                v = *(const float4*)s;
            }
            As[c + 0][r] = v.x; As[c + 1][r] = v.y;
            As[c + 2][r] = v.z; As[c + 3][r] = v.w;
        }
#pragma unroll
        for (int q = 0; q < 2; q++) {
            int slot = tid * 2 + q;
            int r = slot >> 5;
            int c = (slot & 31) * 4;
            int k = kc + r;
            const float* s = (k < 128) ? (Wl + (size_t)k * 128 + c)
                                       : (Wr + (size_t)(k - 128) * 128 + c);
            *(float4*)&Bs[r][c] = *(const float4*)s;
        }
        __syncthreads();
#pragma unroll
        for (int k = 0; k < 16; k++) {
            float4 av0 = *(const float4*)&As[k][trow];
            float4 av1 = *(const float4*)&As[k][trow + 4];
            float4 bv0 = *(const float4*)&Bs[k][tcol];
            float4 bv1 = *(const float4*)&Bs[k][tcol + 4];
            unsigned long long a2[4];
            a2[0] = pack2(av0.x, av0.y); a2[1] = pack2(av0.z, av0.w);
            a2[2] = pack2(av1.x, av1.y); a2[3] = pack2(av1.z, av1.w);
            float bs[8] = {bv0.x, bv0.y, bv0.z, bv0.w, bv1.x, bv1.y, bv1.z, bv1.w};
#pragma unroll
            for (int j = 0; j < 8; j++) {
                unsigned long long bd = dup2(bs[j]);
#pragma unroll
                for (int p = 0; p < 4; p++)
                    acc2[p][j] = ffma2(a2[p], bd, acc2[p][j]);
            }
        }
        __syncthreads();
    }
    float bv[8];
    *(float4*)&bv[0] = *(const float4*)&bias[tcol];
    *(float4*)&bv[4] = *(const float4*)&bias[tcol + 4];
#pragma unroll
    for (int p = 0; p < 4; p++) {
        float lo[8], hi[8];
#pragma unroll
        for (int j = 0; j < 8; j++) unpack2(acc2[p][j], lo[j], hi[j]);
        int row0 = bm + trow + 2 * p;
        if (row0 < NN) {
#pragma unroll
            for (int j = 0; j < 8; j += 4) {
                float4 o;
                o.x = fmaxf(lo[j + 0] + bv[j + 0], 0.f);
                o.y = fmaxf(lo[j + 1] + bv[j + 1], 0.f);
                o.z = fmaxf(lo[j + 2] + bv[j + 2], 0.f);
                o.w = fmaxf(lo[j + 3] + bv[j + 3], 0.f);
                *(float4*)&g_h[(size_t)row0 * 128 + tcol + j] = o;
            }
        }
        if (row0 + 1 < NN) {
#pragma unroll
            for (int j = 0; j < 8; j += 4) {
                float4 o;
                o.x = fmaxf(hi[j + 0] + bv[j + 0], 0.f);
                o.y = fmaxf(hi[j + 1] + bv[j + 1], 0.f);
                o.z = fmaxf(hi[j + 2] + bv[j + 2], 0.f);
                o.w = fmaxf(hi[j + 3] + bv[j + 3], 0.f);
                *(float4*)&g_h[(size_t)(row0 + 1) * 128 + tcol + j] = o;
            }
        }
    }
}

// ---------------- GEMM 2: g_pr = g_h @ [W2_l | W2_r], K=128, N=128 ----------
__global__ __launch_bounds__(256) void k_gemm2(
    const float* __restrict__ W2l, const float* __restrict__ W2r) {
    __shared__ float As[16][128];
    __shared__ float Bs[16][128];
    const int tid = threadIdx.x;
    const int bm = blockIdx.x * 128;
    const int trow = (tid >> 4) * 8;
    const int tcol = (tid & 15) * 8;
    unsigned long long acc2[4][8];
#pragma unroll
    for (int p = 0; p < 4; p++)
#pragma unroll
        for (int j = 0; j < 8; j++) acc2[p][j] = 0ull;

    for (int kc = 0; kc < 128; kc += 16) {
#pragma unroll
        for (int q = 0; q < 2; q++) {
            int slot = tid * 2 + q;
            int r = slot >> 2;
            int c = (slot & 3) * 4;
            int row = bm + r;
            float4 v = make_float4(0.f, 0.f, 0.f, 0.f);
            if (row < NN) v = *(const float4*)(g_h + (size_t)row * 128 + kc + c);
            As[c + 0][r] = v.x; As[c + 1][r] = v.y;
            As[c + 2][r] = v.z; As[c + 3][r] = v.w;
        }
#pragma unroll
        for (int q = 0; q < 2; q++) {
            int slot = tid * 2 + q;
            int r = slot >> 5;
            int c = (slot & 31) * 4;
            int k = kc + r;
            const float* s = (c < 64) ? (W2l + (size_t)k * 64 + c)
                                      : (W2r + (size_t)k * 64 + (c - 64));
            *(float4*)&Bs[r][c] = *(const float4*)s;
        }
        __syncthreads();
#pragma unroll
        for (int k = 0; k < 16; k++) {
            float4 av0 = *(const float4*)&As[k][trow];
            float4 av1 = *(const float4*)&As[k][trow + 4];
            float4 bv0 = *(const float4*)&Bs[k][tcol];
            float4 bv1 = *(const float4*)&Bs[k][tcol + 4];
            unsigned long long a2[4];
            a2[0] = pack2(av0.x, av0.y); a2[1] = pack2(av0.z, av0.w);
            a2[2] = pack2(av1.x, av1.y); a2[3] = pack2(av1.z, av1.w);
            float bs[8] = {bv0.x, bv0.y, bv0.z, bv0.w, bv1.x, bv1.y, bv1.z, bv1.w};
#pragma unroll
            for (int j = 0; j < 8; j++) {
                unsigned long long bd = dup2(bs[j]);
#pragma unroll
                for (int p = 0; p < 4; p++)
                    acc2[p][j] = ffma2(a2[p], bd, acc2[p][j]);
            }
        }
        __syncthreads();
    }
#pragma unroll
    for (int p = 0; p < 4; p++) {
        float lo[8], hi[8];
#pragma unroll
        for (int j = 0; j < 8; j++) unpack2(acc2[p][j], lo[j], hi[j]);
        int row0 = bm + trow + 2 * p;
        if (row0 < NN) {
#pragma unroll
            for (int j = 0; j < 8; j += 4) {
                float4 o = make_float4(lo[j], lo[j + 1], lo[j + 2], lo[j + 3]);
                *(float4*)&g_pr[(size_t)row0 * 128 + tcol + j] = o;
            }
        }
        if (row0 + 1 < NN) {
#pragma unroll
            for (int j = 0; j < 8; j += 4) {
                float4 o = make_float4(hi[j], hi[j + 1], hi[j + 2], hi[j + 3]);
                *(float4*)&g_pr[(size_t)(row0 + 1) * 128 + tcol + j] = o;
            }
        }
    }
}

// ---------------- launch ----------------------------------------------------
extern "C" void kernel_launch(void* const* d_in, const int* in_sizes, int n_in,
                              void* d_out, int out_size) {
    const float*     x   = (const float*)d_in[0];
    const int*       e32 = (const int*)d_in[1];
    const long long* e64 = (const long long*)d_in[1];
    const unsigned*  ew  = (const unsigned*)d_in[1];
    const float*     W1l = (const float*)d_in[2];
    const float*     W1r = (const float*)d_in[3];
    const float*     b1  = (const float*)d_in[4];
    const float*     W2l = (const float*)d_in[5];
    const float*     W2r = (const float*)d_in[6];
    const float*     b2  = (const float*)d_in[7];
    float*           out = (float*)d_out;

    k_detect<<<1, 256>>>(ew);
    k_zero<<<(NN + 255) / 256, 256>>>();
    k_deg<<<(NE / 4 + 255) / 256, 256>>>(e32, e64);
    k_scanA<<<NB_SCAN, 1024>>>();
    k_scanB<<<1, 32>>>();
    k_scanC<<<NB_SCAN, 1024>>>();
    k_scatter<<<(NE / 4 + 255) / 256, 256>>>(e32, e64);

    k_agg128<<<(NN * 32 + 255) / 256, 256>>>(x);                 // agg1 = mean(x)
    k_gemm1<<<(NN + 127) / 128, 256>>>(x, W1l, W1r, b1);         // h
    k_gemm2<<<(NN + 127) / 128, 256>>>(W2l, W2r);                // pr = h@[W2l|W2r]
    k_agg64f<<<(NN * 32 + 255) / 256, 256>>>(b2, out);           // out (fused)
}